// round 14
// baseline (speedup 1.0000x reference)
#include <cuda_runtime.h>
#include <cuda_bf16.h>
#include <math.h>
#include <stdint.h>

#define B_ 2
#define T_ 2048
#define D_ 2048
#define NH 16
#define KH 4
#define HD 128

// ============================================================================
// Scratch (static device globals — no allocation allowed)
// ============================================================================
__device__ uint32_t g_Xq_q1[(size_t)B_ * T_ * (D_ / 4)],  g_Xq_q2[(size_t)B_ * T_ * (D_ / 4)];
__device__ uint32_t g_Xkv_q1[(size_t)B_ * T_ * (D_ / 4)], g_Xkv_q2[(size_t)B_ * T_ * (D_ / 4)];
__device__ uint32_t g_Wq_q1[(size_t)(D_ / 4) * (NH * HD)], g_Wq_q2[(size_t)(D_ / 4) * (NH * HD)];
__device__ uint32_t g_Wkv_q1[(size_t)(D_ / 4) * (2 * KH * HD)], g_Wkv_q2[(size_t)(D_ / 4) * (2 * KH * HD)];
__device__ uint32_t g_Wo_q1[(size_t)((NH * HD) / 4) * D_], g_Wo_q2[(size_t)((NH * HD) / 4) * D_];
__device__ uint32_t g_At_q1[(size_t)B_ * T_ * ((NH * HD) / 4)], g_At_q2[(size_t)B_ * T_ * ((NH * HD) / 4)];
__device__ float g_sXq[B_ * T_], g_sXkv[B_ * T_];
__device__ float g_sWq[NH * HD], g_sWkv[2 * KH * HD], g_sWo[D_];
__device__ uint32_t g_Qh[(size_t)B_ * T_ * NH * 64],  g_Ql[(size_t)B_ * T_ * NH * 64];
__device__ uint32_t g_Kh[(size_t)B_ * T_ * KH * 64],  g_Kl[(size_t)B_ * T_ * KH * 64];
__device__ uint32_t g_Vh[(size_t)B_ * (T_/2) * KH * HD], g_Vl[(size_t)B_ * (T_/2) * KH * HD];

#define AQ_SCALE 8.0f

// ============================================================================
// Helpers
// ============================================================================
__device__ __forceinline__ void split_pair(float a, float b, uint32_t& hi, uint32_t& lo) {
    __nv_bfloat16 ha = __float2bfloat16_rn(a);
    __nv_bfloat16 hb = __float2bfloat16_rn(b);
    float ra = a - __bfloat162float(ha);
    float rb = b - __bfloat162float(hb);
    __nv_bfloat162 h2;
    h2.x = ha; h2.y = hb;
    __nv_bfloat162 l2 = __floats2bfloat162_rn(ra, rb);
    hi = *reinterpret_cast<uint32_t*>(&h2);
    lo = *reinterpret_cast<uint32_t*>(&l2);
}

__device__ __forceinline__ void mma_bf16(float* d, const uint32_t* a, const uint32_t* b) {
    asm volatile(
        "mma.sync.aligned.m16n8k16.row.col.f32.bf16.bf16.f32 "
        "{%0,%1,%2,%3}, {%4,%5,%6,%7}, {%8,%9}, {%0,%1,%2,%3};\n"
        : "+f"(d[0]), "+f"(d[1]), "+f"(d[2]), "+f"(d[3])
        : "r"(a[0]), "r"(a[1]), "r"(a[2]), "r"(a[3]), "r"(b[0]), "r"(b[1]));
}

__device__ __forceinline__ void mma_s8(int* d, const uint32_t* a, const uint32_t* b) {
    asm volatile(
        "mma.sync.aligned.m16n8k32.row.col.s32.s8.s8.s32 "
        "{%0,%1,%2,%3}, {%4,%5,%6,%7}, {%8,%9}, {%0,%1,%2,%3};\n"
        : "+r"(d[0]), "+r"(d[1]), "+r"(d[2]), "+r"(d[3])
        : "r"(a[0]), "r"(a[1]), "r"(a[2]), "r"(a[3]), "r"(b[0]), "r"(b[1]));
}

__device__ __forceinline__ void cp16(uint32_t dst, const void* src) {
    asm volatile("cp.async.ca.shared.global [%0], [%1], 16;\n" ::"r"(dst), "l"(src));
}

__device__ __forceinline__ void quant2(float t, int& q1, int& q2) {
    float q1f = fminf(fmaxf(rintf(t), -127.f), 127.f);
    float r = t - q1f;
    float q2f = fminf(fmaxf(rintf(r * 256.f), -127.f), 127.f);
    q1 = (int)q1f; q2 = (int)q2f;
}

__device__ __forceinline__ void pack4(const int* q, uint32_t& w) {
    w = (uint32_t)(q[0] & 0xFF) | ((uint32_t)(q[1] & 0xFF) << 8)
      | ((uint32_t)(q[2] & 0xFF) << 16) | ((uint32_t)(q[3] & 0xFF) << 24);
}

// ============================================================================
// Quantization prepass kernels
// ============================================================================
__global__ void quant_rows_kernel(const float* __restrict__ X,
                                  uint32_t* __restrict__ Q1, uint32_t* __restrict__ Q2,
                                  float* __restrict__ S, int Kd)
{
    int row = blockIdx.x, tid = threadIdx.x;
    __shared__ float red[256];
    float m = 0.f;
    const float* xr = X + (size_t)row * Kd;
    for (int k = tid; k < Kd; k += 256) m = fmaxf(m, fabsf(xr[k]));
    red[tid] = m; __syncthreads();
    for (int s = 128; s; s >>= 1) {
        if (tid < s) red[tid] = fmaxf(red[tid], red[tid + s]);
        __syncthreads();
    }
    float inv = 127.f / red[0];
    if (tid == 0) S[row] = red[0];
    int words = Kd >> 2;
    for (int w = tid; w < words; w += 256) {
        float4 v = *(const float4*)(xr + 4 * w);
        int q1[4], q2[4];
        quant2(v.x * inv, q1[0], q2[0]);
        quant2(v.y * inv, q1[1], q2[1]);
        quant2(v.z * inv, q1[2], q2[2]);
        quant2(v.w * inv, q1[3], q2[3]);
        uint32_t w1, w2;
        pack4(q1, w1); pack4(q2, w2);
        Q1[(size_t)row * words + w] = w1;
        Q2[(size_t)row * words + w] = w2;
    }
}

__global__ void colmax_kernel(const float* __restrict__ W, float* __restrict__ S,
                              int N, int Kd, int co)
{
    int n = blockIdx.x * 256 + threadIdx.x;
    if (n >= N) return;
    float m = 0.f;
    for (int k = 0; k < Kd; k++) m = fmaxf(m, fabsf(W[(size_t)k * N + n]));
    S[co + n] = m;
}

__global__ void quant_cols_kernel(const float* __restrict__ W,
                                  uint32_t* __restrict__ Q1, uint32_t* __restrict__ Q2,
                                  const float* __restrict__ S,
                                  int N, int ldw, int co, int total)
{
    int i = blockIdx.x * blockDim.x + threadIdx.x;
    if (i >= total) return;
    int kq = i / N, n = i % N;
    float inv = 127.f / S[co + n];
    int q1[4], q2[4];
#pragma unroll
    for (int j = 0; j < 4; j++)
        quant2(W[(size_t)(4 * kq + j) * N + n] * inv, q1[j], q2[j]);
    uint32_t w1, w2;
    pack4(q1, w1); pack4(q2, w2);
    Q1[(size_t)kq * ldw + co + n] = w1;
    Q2[(size_t)kq * ldw + co + n] = w2;
}

// ============================================================================
// int8 EXACT two-limb tensor-core GEMM, 128x128 CTA tile.
// Per 32-k step: 4 IMMA (q1q1 -> P, q1q2+q2q1 -> M, q2q2 -> Q)
// C = sA*sB/127^2 * (P + M/256 + Q/65536)   -- exact 15-bit fixed point
// mode 0: plain fp32 C write (O-proj; sAp==null -> const AQ_SCALE)
// mode 1: RoPE + split -> OH/OL (Q-proj; heads=NH)
// mode 2: KV: head<KH -> RoPE+split K; head>=KH -> V t-pair split
// ============================================================================
#define GA 20
#define GB 136
#define STG_S 130
#define GEMM_SMEM_BYTES ((2 * 128 * GA * 2 + 2 * 16 * GB * 2) * 4)

__global__ void __launch_bounds__(256) s8_gemm_kernel(
    const uint32_t* __restrict__ A1, const uint32_t* __restrict__ A2,
    const uint32_t* __restrict__ B1, const uint32_t* __restrict__ B2,
    const float* __restrict__ sAp, const float* __restrict__ sBp,
    float* __restrict__ C,
    uint32_t* __restrict__ OH, uint32_t* __restrict__ OL,
    uint32_t* __restrict__ VH, uint32_t* __restrict__ VL,
    const int* __restrict__ pos,
    int M, int N, int KPw, int mode)
{
    extern __shared__ uint32_t gs[];
    uint32_t* As1 = gs;
    uint32_t* As2 = As1 + 2 * 128 * GA;
    uint32_t* Bs1 = As2 + 2 * 128 * GA;
    uint32_t* Bs2 = Bs1 + 2 * 16 * GB;

    int bm = blockIdx.y * 128, bn = blockIdx.x * 128;
    int tid = threadIdx.x, warp = tid >> 5, lane = tid & 31;
    int wm = warp & 3, wn = warp >> 2;
    int m0 = wm * 32, n0 = wn * 64;
    int lr = lane >> 2, lc = lane & 3;

    uint32_t sA1 = (uint32_t)__cvta_generic_to_shared(As1);
    uint32_t sA2 = (uint32_t)__cvta_generic_to_shared(As2);
    uint32_t sB1 = (uint32_t)__cvta_generic_to_shared(Bs1);
    uint32_t sB2 = (uint32_t)__cvta_generic_to_shared(Bs2);

    int accP[2][8][4], accM[2][8][4], accQ[2][8][4];
#pragma unroll
    for (int mt = 0; mt < 2; mt++)
#pragma unroll
        for (int nt = 0; nt < 8; nt++)
#pragma unroll
            for (int r = 0; r < 4; r++) {
                accP[mt][nt][r] = 0; accM[mt][nt][r] = 0; accQ[mt][nt][r] = 0;
            }

    auto load_stage = [&](int stage, int kw0) {
        uint32_t aoff = (uint32_t)(stage * 128 * GA) * 4u;
        uint32_t boff = (uint32_t)(stage * 16 * GB) * 4u;
#pragma unroll
        for (int t = 0; t < 2; t++) {
            int c = tid + t * 256;
            int row = c >> 2, seg = (c & 3) << 2;
            size_t src = (size_t)(bm + row) * KPw + kw0 + seg;
            uint32_t dst = (uint32_t)(row * GA + seg) * 4u;
            cp16(sA1 + aoff + dst, A1 + src);
            cp16(sA2 + aoff + dst, A2 + src);
        }
#pragma unroll
        for (int t = 0; t < 2; t++) {
            int c = tid + t * 256;
            int kq = c >> 5, seg = (c & 31) << 2;
            size_t src = (size_t)(kw0 + kq) * N + bn + seg;
            uint32_t dst = (uint32_t)(kq * GB + seg) * 4u;
            cp16(sB1 + boff + dst, B1 + src);
            cp16(sB2 + boff + dst, B2 + src);
        }
        asm volatile("cp.async.commit_group;\n" ::);
    };

    int nK = KPw >> 4;
    load_stage(0, 0);

    for (int kc = 0; kc < nK; kc++) {
        int stage = kc & 1;
        if (kc + 1 < nK) {
            load_stage(stage ^ 1, (kc + 1) << 4);
            asm volatile("cp.async.wait_group 1;\n" ::);
        } else {
            asm volatile("cp.async.wait_group 0;\n" ::);
        }
        __syncthreads();

        const uint32_t* a1 = As1 + stage * 128 * GA;
        const uint32_t* a2 = As2 + stage * 128 * GA;
        const uint32_t* b1 = Bs1 + stage * 16 * GB;
        const uint32_t* b2 = Bs2 + stage * 16 * GB;

#pragma unroll
        for (int ks = 0; ks < 2; ks++) {
            uint32_t fa1[2][4], fa2[2][4];
#pragma unroll
            for (int mt = 0; mt < 2; mt++) {
                int ra = (m0 + mt * 16 + lr) * GA + ks * 8 + lc;
                fa1[mt][0] = a1[ra];     fa1[mt][1] = a1[ra + 8 * GA];
                fa1[mt][2] = a1[ra + 4]; fa1[mt][3] = a1[ra + 8 * GA + 4];
                fa2[mt][0] = a2[ra];     fa2[mt][1] = a2[ra + 8 * GA];
                fa2[mt][2] = a2[ra + 4]; fa2[mt][3] = a2[ra + 8 * GA + 4];
            }
#pragma unroll
            for (int nt = 0; nt < 8; nt++) {
                int kb = (ks * 8 + lc) * GB + n0 + nt * 8 + lr;
                uint32_t fb1[2] = {b1[kb], b1[kb + 4 * GB]};
                uint32_t fb2[2] = {b2[kb], b2[kb + 4 * GB]};
#pragma unroll
                for (int mt = 0; mt < 2; mt++) {
                    mma_s8(accP[mt][nt], fa1[mt], fb1);   // q1*q1
                    mma_s8(accM[mt][nt], fa1[mt], fb2);   // q1*q2
                    mma_s8(accM[mt][nt], fa2[mt], fb1);   // q2*q1
                    mma_s8(accQ[mt][nt], fa2[mt], fb2);   // q2*q2  (exactness)
                }
            }
        }
        __syncthreads();
    }

    const float INV127SQ = 1.f / 16129.f;
    const float INV256 = 1.f / 256.f;
    const float INV65536 = 1.f / 65536.f;

    if (mode == 0) {
#pragma unroll
        for (int mt = 0; mt < 2; mt++) {
            int rlo = bm + m0 + mt * 16 + lr;
            float sa0 = (sAp ? sAp[rlo] : AQ_SCALE) * INV127SQ;
            float sa1 = (sAp ? sAp[rlo + 8] : AQ_SCALE) * INV127SQ;
#pragma unroll
            for (int nt = 0; nt < 8; nt++) {
                int col = bn + n0 + nt * 8 + (lc << 1);
                float sb0 = sBp[col], sb1 = sBp[col + 1];
                float v0 = sa0 * sb0 * ((float)accP[mt][nt][0] + (float)accM[mt][nt][0] * INV256 + (float)accQ[mt][nt][0] * INV65536);
                float v1 = sa0 * sb1 * ((float)accP[mt][nt][1] + (float)accM[mt][nt][1] * INV256 + (float)accQ[mt][nt][1] * INV65536);
                float v2 = sa1 * sb0 * ((float)accP[mt][nt][2] + (float)accM[mt][nt][2] * INV256 + (float)accQ[mt][nt][2] * INV65536);
                float v3 = sa1 * sb1 * ((float)accP[mt][nt][3] + (float)accM[mt][nt][3] * INV256 + (float)accQ[mt][nt][3] * INV65536);
                *(float2*)(C + (size_t)rlo * N + col) = make_float2(v0, v1);
                *(float2*)(C + (size_t)(rlo + 8) * N + col) = make_float2(v2, v3);
            }
        }
        return;
    }

    float* stg = (float*)gs;
#pragma unroll
    for (int mt = 0; mt < 2; mt++) {
        int r = m0 + mt * 16 + lr;
        float sa0 = sAp[bm + r] * INV127SQ;
        float sa1 = sAp[bm + r + 8] * INV127SQ;
#pragma unroll
        for (int nt = 0; nt < 8; nt++) {
            int cpair = n0 + nt * 8 + (lc << 1);
            float sb0 = sBp[bn + cpair], sb1 = sBp[bn + cpair + 1];
            float v0 = sa0 * sb0 * ((float)accP[mt][nt][0] + (float)accM[mt][nt][0] * INV256 + (float)accQ[mt][nt][0] * INV65536);
            float v1 = sa0 * sb1 * ((float)accP[mt][nt][1] + (float)accM[mt][nt][1] * INV256 + (float)accQ[mt][nt][1] * INV65536);
            float v2 = sa1 * sb0 * ((float)accP[mt][nt][2] + (float)accM[mt][nt][2] * INV256 + (float)accQ[mt][nt][2] * INV65536);
            float v3 = sa1 * sb1 * ((float)accP[mt][nt][3] + (float)accM[mt][nt][3] * INV256 + (float)accQ[mt][nt][3] * INV65536);
            *(float2*)&stg[r * STG_S + cpair] = make_float2(v0, v1);
            *(float2*)&stg[(r + 8) * STG_S + cpair] = make_float2(v2, v3);
        }
    }
    __syncthreads();

    int head = bn >> 7;
    if (mode == 1 || head < KH) {
        int heads = (mode == 1) ? NH : KH;
        for (int t = 0; t < 16; t++) {
            int i = tid + t * 256;
            int j = i & 31, r = i >> 5;
            int bt = bm + r;
            float p = (float)pos[bt];
            float s0, c0, s1, c1;
            float ts0 = powf(10000.f, (float)(4 * j) / 128.f);
            sincosf(p / ts0, &s0, &c0);
            float ts1 = powf(10000.f, (float)(4 * j + 2) / 128.f);
            sincosf(p / ts1, &s1, &c1);
            float a0 = stg[r * STG_S + 2 * j],      a1 = stg[r * STG_S + 2 * j + 1];
            float b0 = stg[r * STG_S + 2 * j + 64], b1 = stg[r * STG_S + 2 * j + 65];
            float o10 = a0 * c0 - b0 * s0, o11 = a1 * c1 - b1 * s1;
            float o20 = b0 * c0 + a0 * s0, o21 = b1 * c1 + a1 * s1;
            size_t ob = ((size_t)bt * heads + head) * 64;
            uint32_t hh, ll;
            split_pair(o10, o11, hh, ll); OH[ob + j] = hh;      OL[ob + j] = ll;
            split_pair(o20, o21, hh, ll); OH[ob + 32 + j] = hh; OL[ob + 32 + j] = ll;
        }
    } else {
        int k = head - KH;
        for (int t = 0; t < 32; t++) {
            int i = tid + t * 256;
            int h = i & 127, tp_l = i >> 7;
            int gt = bm + 2 * tp_l;
            int b = gt >> 11;
            int tp = (gt - b * T_) >> 1;
            float va = stg[(2 * tp_l) * STG_S + h];
            float vb = stg[(2 * tp_l + 1) * STG_S + h];
            uint32_t hh, ll;
            split_pair(va, vb, hh, ll);
            size_t oi = (((size_t)(b * (T_ / 2) + tp)) * KH + k) * 128 + h;
            VH[oi] = hh; VL[oi] = ll;
        }
    }
}

// ============================================================================
// Tensor-core causal flash attention — bf16 hi/lo in, int8 two-limb quant out.
// ============================================================================
#define QS_STRIDE 68
#define VS_STRIDE 132
#define SS_STRIDE 66
#define FLASH_SMEM_BYTES ((4 * 64 * QS_STRIDE + 2 * 32 * VS_STRIDE + 64 * SS_STRIDE + 192) * 4)

__global__ void __launch_bounds__(256) flash_kernel(
    const uint32_t* __restrict__ Qh, const uint32_t* __restrict__ Ql,
    const uint32_t* __restrict__ Kh, const uint32_t* __restrict__ Kl,
    const uint32_t* __restrict__ Vh, const uint32_t* __restrict__ Vl,
    uint16_t* __restrict__ Atq1, uint16_t* __restrict__ Atq2)
{
    extern __shared__ uint32_t smw[];
    uint32_t* QsH = smw;
    uint32_t* QsL = QsH + 64 * QS_STRIDE;
    uint32_t* KsH = QsL + 64 * QS_STRIDE;
    uint32_t* KsL = KsH + 64 * QS_STRIDE;
    uint32_t* VsH = KsL + 64 * QS_STRIDE;
    uint32_t* VsL = VsH + 32 * VS_STRIDE;
    float* Ss   = (float*)(VsL + 32 * VS_STRIDE);
    float* mrow = Ss + 64 * SS_STRIDE;
    float* lrow = mrow + 64;
    float* arow = lrow + 64;

    int qt = blockIdx.x, n = blockIdx.y, b = blockIdx.z;
    int kvh = n >> 2;
    int tid = threadIdx.x, lane = tid & 31, warp = tid >> 5;
    int wq = warp & 3, wc = warp >> 2;
    int lr = lane >> 2, lc = lane & 3;
    const float scale = 0.08838834764831844f;

    int r0 = wq * 16;
    int n0 = wc * 32;
    int h0c = wc * 64;

    for (int i = tid; i < 64 * 16; i += 256) {
        int r = i >> 4, c4 = (i & 15) << 2;
        size_t g = (((size_t)(b * T_ + qt * 64 + r)) * NH + n) * 64 + c4;
        *(uint4*)&QsH[r * QS_STRIDE + c4] = *(const uint4*)(Qh + g);
        *(uint4*)&QsL[r * QS_STRIDE + c4] = *(const uint4*)(Ql + g);
    }
    if (tid < 64) { mrow[tid] = -1e30f; lrow[tid] = 0.f; }

    float o[8][4];
#pragma unroll
    for (int nt = 0; nt < 8; nt++)
#pragma unroll
        for (int r = 0; r < 4; r++) o[nt][r] = 0.f;

    int row = tid >> 2, part = tid & 3;

    for (int kt = 0; kt <= qt; ++kt) {
        __syncthreads();

        for (int i = tid; i < 64 * 16; i += 256) {
            int r = i >> 4, c4 = (i & 15) << 2;
            size_t g = (((size_t)(b * T_ + kt * 64 + r)) * KH + kvh) * 64 + c4;
            *(uint4*)&KsH[r * QS_STRIDE + c4] = *(const uint4*)(Kh + g);
            *(uint4*)&KsL[r * QS_STRIDE + c4] = *(const uint4*)(Kl + g);
        }
        for (int i = tid; i < 32 * 32; i += 256) {
            int kp = i >> 5, h4 = (i & 31) << 2;
            size_t g = (((size_t)(b * (T_ / 2) + kt * 32 + kp)) * KH + kvh) * HD + h4;
            *(uint4*)&VsH[kp * VS_STRIDE + h4] = *(const uint4*)(Vh + g);
            *(uint4*)&VsL[kp * VS_STRIDE + h4] = *(const uint4*)(Vl + g);
        }
        __syncthreads();

        float s[4][4];
#pragma unroll
        for (int nt = 0; nt < 4; nt++)
#pragma unroll
            for (int r = 0; r < 4; r++) s[nt][r] = 0.f;

#pragma unroll
        for (int kc = 0; kc < 8; kc++) {
            int pa = 8 * kc + lc;
            int ra = (r0 + lr) * QS_STRIDE, rb = (r0 + 8 + lr) * QS_STRIDE;
            uint32_t aH[4], aL[4];
            aH[0] = QsH[ra + pa];     aH[1] = QsH[rb + pa];
            aH[2] = QsH[ra + pa + 4]; aH[3] = QsH[rb + pa + 4];
            aL[0] = QsL[ra + pa];     aL[1] = QsL[rb + pa];
            aL[2] = QsL[ra + pa + 4]; aL[3] = QsL[rb + pa + 4];
#pragma unroll
            for (int nt = 0; nt < 4; nt++) {
                int nn = (n0 + nt * 8 + lr) * QS_STRIDE;
                uint32_t bH[2] = {KsH[nn + pa], KsH[nn + pa + 4]};
                uint32_t bL[2] = {KsL[nn + pa], KsL[nn + pa + 4]};
                mma_bf16(s[nt], aH, bH);
                mma_bf16(s[nt], aH, bL);
                mma_bf16(s[nt], aL, bH);
            }
        }

        bool diag = (kt == qt);
        int rq0 = r0 + lr, rq1 = r0 + 8 + lr;
#pragma unroll
        for (int nt = 0; nt < 4; nt++) {
            int col = n0 + nt * 8 + (lc << 1);
            float v0 = s[nt][0] * scale, v1 = s[nt][1] * scale;
            float v2 = s[nt][2] * scale, v3 = s[nt][3] * scale;
            if (diag) {
                if (col     > rq0) v0 = -1e30f;
                if (col + 1 > rq0) v1 = -1e30f;
                if (col     > rq1) v2 = -1e30f;
                if (col + 1 > rq1) v3 = -1e30f;
            }
            Ss[rq0 * SS_STRIDE + col]     = v0;
            Ss[rq0 * SS_STRIDE + col + 1] = v1;
            Ss[rq1 * SS_STRIDE + col]     = v2;
            Ss[rq1 * SS_STRIDE + col + 1] = v3;
        }
        __syncthreads();

        float mx = -1e30f;
#pragma unroll
        for (int c = 0; c < 16; ++c)
            mx = fmaxf(mx, Ss[row * SS_STRIDE + part * 16 + c]);
        mx = fmaxf(mx, __shfl_xor_sync(0xffffffffu, mx, 1));
        mx = fmaxf(mx, __shfl_xor_sync(0xffffffffu, mx, 2));
        float m_old = mrow[row];
        float m_new = fmaxf(m_old, mx);
        float sum = 0.f;
#pragma unroll
        for (int c = 0; c < 16; ++c) {
            float p = __expf(Ss[row * SS_STRIDE + part * 16 + c] - m_new);
            Ss[row * SS_STRIDE + part * 16 + c] = p;
            sum += p;
        }
        sum += __shfl_xor_sync(0xffffffffu, sum, 1);
        sum += __shfl_xor_sync(0xffffffffu, sum, 2);
        if (part == 0) {
            float alpha = __expf(m_old - m_new);
            arow[row] = alpha;
            mrow[row] = m_new;
            lrow[row] = lrow[row] * alpha + sum;
        }
        __syncthreads();

        float al0 = arow[rq0], al1 = arow[rq1];
#pragma unroll
        for (int nt = 0; nt < 8; nt++) {
            o[nt][0] *= al0; o[nt][1] *= al0;
            o[nt][2] *= al1; o[nt][3] *= al1;
        }

#pragma unroll
        for (int kc = 0; kc < 4; kc++) {
            int ka = 16 * kc + (lc << 1);
            float2 p00 = *(float2*)&Ss[rq0 * SS_STRIDE + ka];
            float2 p01 = *(float2*)&Ss[rq0 * SS_STRIDE + ka + 8];
            float2 p10 = *(float2*)&Ss[rq1 * SS_STRIDE + ka];
            float2 p11 = *(float2*)&Ss[rq1 * SS_STRIDE + ka + 8];
            uint32_t aH[4], aL[4];
            split_pair(p00.x, p00.y, aH[0], aL[0]);
            split_pair(p10.x, p10.y, aH[1], aL[1]);
            split_pair(p01.x, p01.y, aH[2], aL[2]);
            split_pair(p11.x, p11.y, aH[3], aL[3]);
#pragma unroll
            for (int nt = 0; nt < 8; nt++) {
                int nn = h0c + nt * 8 + lr;
                int kpb = 8 * kc + lc;
                uint32_t bH[2] = {VsH[kpb * VS_STRIDE + nn], VsH[(kpb + 4) * VS_STRIDE + nn]};
                uint32_t bL[2] = {VsL[kpb * VS_STRIDE + nn], VsL[(kpb + 4) * VS_STRIDE + nn]};
                mma_bf16(o[nt], aH, bH);
                mma_bf16(o[nt], aH, bL);
                mma_bf16(o[nt], aL, bH);
            }
        }
    }

    int rq0 = r0 + lr, rq1 = r0 + 8 + lr;
    float li0 = 1.f / lrow[rq0], li1 = 1.f / lrow[rq1];
    const float qinv = 127.f / AQ_SCALE;
    size_t ub0 = (size_t)(b * T_ + qt * 64 + rq0) * 1024 + n * 64;
    size_t ub1 = (size_t)(b * T_ + qt * 64 + rq1) * 1024 + n * 64;
#pragma unroll
    for (int nt = 0; nt < 8; nt++) {
        int cw = ((h0c + nt * 8) >> 1) + lc;
        int qa, qb, q2a, q2b;
        quant2(o[nt][0] * li0 * qinv, qa, q2a);
        quant2(o[nt][1] * li0 * qinv, qb, q2b);
        Atq1[ub0 + cw] = (uint16_t)((qa & 0xFF) | ((qb & 0xFF) << 8));
        Atq2[ub0 + cw] = (uint16_t)((q2a & 0xFF) | ((q2b & 0xFF) << 8));
        quant2(o[nt][2] * li1 * qinv, qa, q2a);
        quant2(o[nt][3] * li1 * qinv, qb, q2b);
        Atq1[ub1 + cw] = (uint16_t)((qa & 0xFF) | ((qb & 0xFF) << 8));
        Atq2[ub1 + cw] = (uint16_t)((q2a & 0xFF) | ((q2b & 0xFF) << 8));
    }
}

// ============================================================================
// Launch
// ============================================================================
extern "C" void kernel_launch(void* const* d_in, const int* in_sizes, int n_in,
                              void* d_out, int out_size)
{
    const float* Xq  = (const float*)d_in[0];
    const float* Xkv = (const float*)d_in[1];
    const int* qpos  = (const int*)d_in[2];
    const int* kvpos = (const int*)d_in[3];
    const float* Wq  = (const float*)d_in[4];
    const float* Wk  = (const float*)d_in[5];
    const float* Wv  = (const float*)d_in[6];
    const float* Wo  = (const float*)d_in[7];
    float* out = (float*)d_out;

    uint32_t *pXq1, *pXq2, *pXkv1, *pXkv2, *pWq1, *pWq2, *pWkv1, *pWkv2, *pWo1, *pWo2;
    uint32_t *pAt1, *pAt2, *pQh, *pQl, *pKh, *pKl, *pVh, *pVl;
    float *psXq, *psXkv, *psWq, *psWkv, *psWo;
    cudaGetSymbolAddress((void**)&pXq1, g_Xq_q1);   cudaGetSymbolAddress((void**)&pXq2, g_Xq_q2);
    cudaGetSymbolAddress((void**)&pXkv1, g_Xkv_q1); cudaGetSymbolAddress((void**)&pXkv2, g_Xkv_q2);
    cudaGetSymbolAddress((void**)&pWq1, g_Wq_q1);   cudaGetSymbolAddress((void**)&pWq2, g_Wq_q2);
    cudaGetSymbolAddress((void**)&pWkv1, g_Wkv_q1); cudaGetSymbolAddress((void**)&pWkv2, g_Wkv_q2);
    cudaGetSymbolAddress((void**)&pWo1, g_Wo_q1);   cudaGetSymbolAddress((void**)&pWo2, g_Wo_q2);
    cudaGetSymbolAddress((void**)&pAt1, g_At_q1);   cudaGetSymbolAddress((void**)&pAt2, g_At_q2);
    cudaGetSymbolAddress((void**)&pQh, g_Qh);       cudaGetSymbolAddress((void**)&pQl, g_Ql);
    cudaGetSymbolAddress((void**)&pKh, g_Kh);       cudaGetSymbolAddress((void**)&pKl, g_Kl);
    cudaGetSymbolAddress((void**)&pVh, g_Vh);       cudaGetSymbolAddress((void**)&pVl, g_Vl);
    cudaGetSymbolAddress((void**)&psXq, g_sXq);     cudaGetSymbolAddress((void**)&psXkv, g_sXkv);
    cudaGetSymbolAddress((void**)&psWq, g_sWq);     cudaGetSymbolAddress((void**)&psWkv, g_sWkv);
    cudaGetSymbolAddress((void**)&psWo, g_sWo);

    cudaFuncSetAttribute(flash_kernel,
                         cudaFuncAttributeMaxDynamicSharedMemorySize, FLASH_SMEM_BYTES);
    cudaFuncSetAttribute(s8_gemm_kernel,
                         cudaFuncAttributeMaxDynamicSharedMemorySize, GEMM_SMEM_BYTES);

    int M = B_ * T_;  // 4096

    // --- Quantization prepass ---
    quant_rows_kernel<<<M, 256>>>(Xq, pXq1, pXq2, psXq, D_);
    quant_rows_kernel<<<M, 256>>>(Xkv, pXkv1, pXkv2, psXkv, D_);
    colmax_kernel<<<(NH * HD + 255) / 256, 256>>>(Wq, psWq, NH * HD, D_, 0);
    colmax_kernel<<<(KH * HD + 255) / 256, 256>>>(Wk, psWkv, KH * HD, D_, 0);
    colmax_kernel<<<(KH * HD + 255) / 256, 256>>>(Wv, psWkv, KH * HD, D_, KH * HD);
    colmax_kernel<<<(D_ + 255) / 256, 256>>>(Wo, psWo, D_, NH * HD, 0);
    int tWq = (D_ / 4) * (NH * HD);
    quant_cols_kernel<<<(tWq + 255) / 256, 256>>>(Wq, pWq1, pWq2, psWq, NH * HD, NH * HD, 0, tWq);
    int tWk = (D_ / 4) * (KH * HD);
    quant_cols_kernel<<<(tWk + 255) / 256, 256>>>(Wk, pWkv1, pWkv2, psWkv, KH * HD, 2 * KH * HD, 0, tWk);
    quant_cols_kernel<<<(tWk + 255) / 256, 256>>>(Wv, pWkv1, pWkv2, psWkv, KH * HD, 2 * KH * HD, KH * HD, tWk);
    int tWo = ((NH * HD) / 4) * D_;
    quant_cols_kernel<<<(tWo + 255) / 256, 256>>>(Wo, pWo1, pWo2, psWo, D_, D_, 0, tWo);

    // --- Q projection + fused RoPE/split ---
    s8_gemm_kernel<<<dim3((NH * HD) / 128, M / 128), 256, GEMM_SMEM_BYTES>>>(
        pXq1, pXq2, pWq1, pWq2, psXq, psWq,
        nullptr, pQh, pQl, nullptr, nullptr, qpos,
        M, NH * HD, D_ / 4, 1);

    // --- KV projection + fused RoPE-K / V-pair split ---
    s8_gemm_kernel<<<dim3((2 * KH * HD) / 128, M / 128), 256, GEMM_SMEM_BYTES>>>(
        pXkv1, pXkv2, pWkv1, pWkv2, psXkv, psWkv,
        nullptr, pKh, pKl, pVh, pVl, kvpos,
        M, 2 * KH * HD, D_ / 4, 2);

    // --- Flash attention (bf16 3-product, int8 quant epilogue) ---
    flash_kernel<<<dim3(T_ / 64, NH, B_), 256, FLASH_SMEM_BYTES>>>(
        pQh, pQl, pKh, pKl, pVh, pVl, (uint16_t*)pAt1, (uint16_t*)pAt2);

    // --- O projection (fp32 out) ---
    s8_gemm_kernel<<<dim3(D_ / 128, M / 128), 256, GEMM_SMEM_BYTES>>>(
        pAt1, pAt2, pWo1, pWo2, nullptr, psWo,
        out, nullptr, nullptr, nullptr, nullptr, nullptr,
        M, D_, (NH * HD) / 4, 0);
}

// round 15
// speedup vs baseline: 3.0843x; 3.0843x over previous
#include <cuda_runtime.h>
#include <cuda_bf16.h>
#include <cuda_fp16.h>
#include <math.h>
#include <stdint.h>

#define B_ 2
#define T_ 2048
#define D_ 2048
#define NH 16
#define KH 4
#define HD 128

// ============================================================================
// Scratch (static device globals — no allocation allowed)
// ============================================================================
// fp16 GEMM operands: A single-limb (hi only), B two-limb (hi/lo)
__device__ uint32_t g_Xq_h[(size_t)B_ * T_ * D_ / 2];                  // fp16x2 words
__device__ uint32_t g_Xkv_h[(size_t)B_ * T_ * D_ / 2];
__device__ uint32_t g_Wq_h[(size_t)D_ / 2 * (NH * HD)], g_Wq_l[(size_t)D_ / 2 * (NH * HD)];
__device__ uint32_t g_Wkv_h[(size_t)D_ / 2 * (2 * KH * HD)], g_Wkv_l[(size_t)D_ / 2 * (2 * KH * HD)];
__device__ uint32_t g_Wo_h[(size_t)(NH * HD) / 2 * D_], g_Wo_l[(size_t)(NH * HD) / 2 * D_];
__device__ uint32_t g_At_h[(size_t)B_ * T_ * NH * 64];                 // attn fp16x2 words
// flash-format bf16 hi/lo buffers (written by projection epilogues)
__device__ uint32_t g_Qh[(size_t)B_ * T_ * NH * 64],  g_Ql[(size_t)B_ * T_ * NH * 64];
__device__ uint32_t g_Kh[(size_t)B_ * T_ * KH * 64],  g_Kl[(size_t)B_ * T_ * KH * 64];
__device__ uint32_t g_Vh[(size_t)B_ * (T_/2) * KH * HD], g_Vl[(size_t)B_ * (T_/2) * KH * HD];

// ============================================================================
// Helpers
// ============================================================================
// bf16 hi/lo split (flash path — unchanged, proven)
__device__ __forceinline__ void split_pair(float a, float b, uint32_t& hi, uint32_t& lo) {
    __nv_bfloat16 ha = __float2bfloat16_rn(a);
    __nv_bfloat16 hb = __float2bfloat16_rn(b);
    float ra = a - __bfloat162float(ha);
    float rb = b - __bfloat162float(hb);
    __nv_bfloat162 h2;
    h2.x = ha; h2.y = hb;
    __nv_bfloat162 l2 = __floats2bfloat162_rn(ra, rb);
    hi = *reinterpret_cast<uint32_t*>(&h2);
    lo = *reinterpret_cast<uint32_t*>(&l2);
}

// fp16 hi/lo split (GEMM B operands)
__device__ __forceinline__ void split_pair_h(float a, float b, uint32_t& hi, uint32_t& lo) {
    __half ha = __float2half_rn(a);
    __half hb = __float2half_rn(b);
    float ra = a - __half2float(ha);
    float rb = b - __half2float(hb);
    __half2 h2; h2.x = ha; h2.y = hb;
    __half2 l2 = __floats2half2_rn(ra, rb);
    hi = *reinterpret_cast<uint32_t*>(&h2);
    lo = *reinterpret_cast<uint32_t*>(&l2);
}

__device__ __forceinline__ void mma_bf16(float* d, const uint32_t* a, const uint32_t* b) {
    asm volatile(
        "mma.sync.aligned.m16n8k16.row.col.f32.bf16.bf16.f32 "
        "{%0,%1,%2,%3}, {%4,%5,%6,%7}, {%8,%9}, {%0,%1,%2,%3};\n"
        : "+f"(d[0]), "+f"(d[1]), "+f"(d[2]), "+f"(d[3])
        : "r"(a[0]), "r"(a[1]), "r"(a[2]), "r"(a[3]), "r"(b[0]), "r"(b[1]));
}

__device__ __forceinline__ void mma_f16(float* d, const uint32_t* a, const uint32_t* b) {
    asm volatile(
        "mma.sync.aligned.m16n8k16.row.col.f32.f16.f16.f32 "
        "{%0,%1,%2,%3}, {%4,%5,%6,%7}, {%8,%9}, {%0,%1,%2,%3};\n"
        : "+f"(d[0]), "+f"(d[1]), "+f"(d[2]), "+f"(d[3])
        : "r"(a[0]), "r"(a[1]), "r"(a[2]), "r"(a[3]), "r"(b[0]), "r"(b[1]));
}

__device__ __forceinline__ void cp16(uint32_t dst, const void* src) {
    asm volatile("cp.async.ca.shared.global [%0], [%1], 16;\n" ::"r"(dst), "l"(src));
}

// ============================================================================
// Prepass kernels
// ============================================================================
// X -> fp16x2 words [R][C/2] (single limb; A operand)
__global__ void f16_rowpair_kernel(const float* __restrict__ X,
                                   uint32_t* __restrict__ H, int total_words)
{
    int i = blockIdx.x * blockDim.x + threadIdx.x;
    if (i >= total_words) return;
    float2 v = *(const float2*)(X + 2 * (size_t)i);
    __half2 h2 = __floats2half2_rn(v.x, v.y);
    H[i] = *reinterpret_cast<uint32_t*>(&h2);
}

// W [Kd][N] -> fp16 hi/lo words [Kd/2][ldw] at col offset co (k-paired)
__global__ void f16_colpair_kernel(const float* __restrict__ X,
                                   uint32_t* __restrict__ H, uint32_t* __restrict__ L,
                                   int N, int ldw, int co, int total)
{
    int i = blockIdx.x * blockDim.x + threadIdx.x;
    if (i >= total) return;
    int kp = i / N, n = i % N;
    float a = X[(size_t)(2 * kp) * N + n];
    float b = X[(size_t)(2 * kp + 1) * N + n];
    uint32_t h, l;
    split_pair_h(a, b, h, l);
    H[(size_t)kp * ldw + co + n] = h;
    L[(size_t)kp * ldw + co + n] = l;
}

// ============================================================================
// fp16 2-product GEMM (A single-limb fp16, B two-limb fp16), 256x128 CTA tile.
// acc += aH*bH + aH*bL  (dropped aL*b ~ 2^-12 relative)
// mode 0: plain fp32 C write (O-proj)
// mode 1: RoPE + bf16-split -> OH/OL (Q-proj; heads=NH)
// mode 2: KV: head<KH -> RoPE+bf16-split K; head>=KH -> V t-pair bf16-split
// ============================================================================
#define GA 20
#define GB 136
#define STG_S 130
#define GEMM_SMEM_BYTES (256 * STG_S * 4)   // 133120 (>= mainloop's 75776)

__global__ void __launch_bounds__(256) f16p_gemm_kernel(
    const uint32_t* __restrict__ Ah,
    const uint32_t* __restrict__ Bh, const uint32_t* __restrict__ Bl,
    float* __restrict__ C,
    uint32_t* __restrict__ OH, uint32_t* __restrict__ OL,
    uint32_t* __restrict__ VH, uint32_t* __restrict__ VL,
    const int* __restrict__ pos,
    int M, int N, int KP, int mode)
{
    extern __shared__ uint32_t gs[];
    uint32_t* AsH = gs;                      // [2][256*GA]
    uint32_t* BsH = AsH + 2 * 256 * GA;      // [2][16*GB]
    uint32_t* BsL = BsH + 2 * 16 * GB;

    int bm = blockIdx.y * 256, bn = blockIdx.x * 128;
    int tid = threadIdx.x, warp = tid >> 5, lane = tid & 31;
    int wm = warp & 3, wn = warp >> 2;
    int m0 = wm * 64, n0 = wn * 64;
    int lr = lane >> 2, lc = lane & 3;

    uint32_t sAH = (uint32_t)__cvta_generic_to_shared(AsH);
    uint32_t sBH = (uint32_t)__cvta_generic_to_shared(BsH);
    uint32_t sBL = (uint32_t)__cvta_generic_to_shared(BsL);

    float acc[4][8][4];
#pragma unroll
    for (int mt = 0; mt < 4; mt++)
#pragma unroll
        for (int nt = 0; nt < 8; nt++)
#pragma unroll
            for (int r = 0; r < 4; r++) acc[mt][nt][r] = 0.f;

    auto load_stage = [&](int stage, int kp0) {
        uint32_t aoff = (uint32_t)(stage * 256 * GA) * 4u;
        uint32_t boff = (uint32_t)(stage * 16 * GB) * 4u;
#pragma unroll
        for (int t = 0; t < 4; t++) {
            int c = tid + t * 256;
            int row = c >> 2, seg = (c & 3) << 2;   // 256 rows x 16 words
            size_t src = (size_t)(bm + row) * KP + kp0 + seg;
            cp16(sAH + aoff + (uint32_t)(row * GA + seg) * 4u, Ah + src);
        }
#pragma unroll
        for (int t = 0; t < 2; t++) {
            int c = tid + t * 256;
            int kp = c >> 5, seg = (c & 31) << 2;   // 16 kp x 128 words
            size_t src = (size_t)(kp0 + kp) * N + bn + seg;
            uint32_t dst = (uint32_t)(kp * GB + seg) * 4u;
            cp16(sBH + boff + dst, Bh + src);
            cp16(sBL + boff + dst, Bl + src);
        }
        asm volatile("cp.async.commit_group;\n" ::);
    };

    int nK = KP >> 4;
    load_stage(0, 0);

    for (int kc = 0; kc < nK; kc++) {
        int stage = kc & 1;
        if (kc + 1 < nK) {
            load_stage(stage ^ 1, (kc + 1) << 4);
            asm volatile("cp.async.wait_group 1;\n" ::);
        } else {
            asm volatile("cp.async.wait_group 0;\n" ::);
        }
        __syncthreads();

        const uint32_t* aH = AsH + stage * 256 * GA;
        const uint32_t* bH = BsH + stage * 16 * GB;
        const uint32_t* bL = BsL + stage * 16 * GB;

#pragma unroll
        for (int ks = 0; ks < 2; ks++) {
            uint32_t fah[4][4];
#pragma unroll
            for (int mt = 0; mt < 4; mt++) {
                int ra = (m0 + mt * 16 + lr) * GA + ks * 8 + lc;
                fah[mt][0] = aH[ra];     fah[mt][1] = aH[ra + 8 * GA];
                fah[mt][2] = aH[ra + 4]; fah[mt][3] = aH[ra + 8 * GA + 4];
            }
#pragma unroll
            for (int nt = 0; nt < 8; nt++) {
                int kb = (ks * 8 + lc) * GB + n0 + nt * 8 + lr;
                uint32_t fbh[2] = {bH[kb], bH[kb + 4 * GB]};
                uint32_t fbl[2] = {bL[kb], bL[kb + 4 * GB]};
#pragma unroll
                for (int mt = 0; mt < 4; mt++) {
                    mma_f16(acc[mt][nt], fah[mt], fbh);   // hi*hi
                    mma_f16(acc[mt][nt], fah[mt], fbl);   // hi*lo
                }
            }
        }
        __syncthreads();
    }

    if (mode == 0) {
#pragma unroll
        for (int mt = 0; mt < 4; mt++) {
            int row = bm + m0 + mt * 16 + lr;
#pragma unroll
            for (int nt = 0; nt < 8; nt++) {
                int col = bn + n0 + nt * 8 + (lc << 1);
                *(float2*)(C + (size_t)row * N + col) = make_float2(acc[mt][nt][0], acc[mt][nt][1]);
                *(float2*)(C + (size_t)(row + 8) * N + col) = make_float2(acc[mt][nt][2], acc[mt][nt][3]);
            }
        }
        return;
    }

    // Stage fp32 tile (256 x 128) in smem, then convert in fused epilogue.
    float* stg = (float*)gs;
#pragma unroll
    for (int mt = 0; mt < 4; mt++) {
        int r = m0 + mt * 16 + lr;
#pragma unroll
        for (int nt = 0; nt < 8; nt++) {
            int cpair = n0 + nt * 8 + (lc << 1);
            *(float2*)&stg[r * STG_S + cpair] = make_float2(acc[mt][nt][0], acc[mt][nt][1]);
            *(float2*)&stg[(r + 8) * STG_S + cpair] = make_float2(acc[mt][nt][2], acc[mt][nt][3]);
        }
    }
    __syncthreads();

    int head = bn >> 7;
    if (mode == 1 || head < KH) {
        int heads = (mode == 1) ? NH : KH;
        for (int t = 0; t < 32; t++) {
            int i = tid + t * 256;
            int j = i & 31, r = i >> 5;
            int bt = bm + r;
            float p = (float)pos[bt];
            float s0, c0, s1, c1;
            float ts0 = powf(10000.f, (float)(4 * j) / 128.f);
            sincosf(p / ts0, &s0, &c0);
            float ts1 = powf(10000.f, (float)(4 * j + 2) / 128.f);
            sincosf(p / ts1, &s1, &c1);
            float a0 = stg[r * STG_S + 2 * j],      a1 = stg[r * STG_S + 2 * j + 1];
            float b0 = stg[r * STG_S + 2 * j + 64], b1 = stg[r * STG_S + 2 * j + 65];
            float o10 = a0 * c0 - b0 * s0, o11 = a1 * c1 - b1 * s1;
            float o20 = b0 * c0 + a0 * s0, o21 = b1 * c1 + a1 * s1;
            size_t ob = ((size_t)bt * heads + head) * 64;
            uint32_t hh, ll;
            split_pair(o10, o11, hh, ll); OH[ob + j] = hh;      OL[ob + j] = ll;
            split_pair(o20, o21, hh, ll); OH[ob + 32 + j] = hh; OL[ob + 32 + j] = ll;
        }
    } else {
        int k = head - KH;
        for (int t = 0; t < 64; t++) {
            int i = tid + t * 256;
            int h = i & 127, tp_l = i >> 7;
            int gt = bm + 2 * tp_l;
            int b = gt >> 11;
            int tp = (gt - b * T_) >> 1;
            float va = stg[(2 * tp_l) * STG_S + h];
            float vb = stg[(2 * tp_l + 1) * STG_S + h];
            uint32_t hh, ll;
            split_pair(va, vb, hh, ll);
            size_t oi = (((size_t)(b * (T_ / 2) + tp)) * KH + k) * 128 + h;
            VH[oi] = hh; VL[oi] = ll;
        }
    }
}

// ============================================================================
// Tensor-core causal flash attention — bf16 hi/lo in, fp16 attn out (R11 core).
// ============================================================================
#define QS_STRIDE 68
#define VS_STRIDE 132
#define SS_STRIDE 66
#define FLASH_SMEM_BYTES ((4 * 64 * QS_STRIDE + 2 * 32 * VS_STRIDE + 64 * SS_STRIDE + 192) * 4)

__global__ void __launch_bounds__(256) flash_kernel(
    const uint32_t* __restrict__ Qh, const uint32_t* __restrict__ Ql,
    const uint32_t* __restrict__ Kh, const uint32_t* __restrict__ Kl,
    const uint32_t* __restrict__ Vh, const uint32_t* __restrict__ Vl,
    uint32_t* __restrict__ At)
{
    extern __shared__ uint32_t smw[];
    uint32_t* QsH = smw;
    uint32_t* QsL = QsH + 64 * QS_STRIDE;
    uint32_t* KsH = QsL + 64 * QS_STRIDE;
    uint32_t* KsL = KsH + 64 * QS_STRIDE;
    uint32_t* VsH = KsL + 64 * QS_STRIDE;
    uint32_t* VsL = VsH + 32 * VS_STRIDE;
    float* Ss   = (float*)(VsL + 32 * VS_STRIDE);
    float* mrow = Ss + 64 * SS_STRIDE;
    float* lrow = mrow + 64;
    float* arow = lrow + 64;

    int qt = blockIdx.x, n = blockIdx.y, b = blockIdx.z;
    int kvh = n >> 2;
    int tid = threadIdx.x, lane = tid & 31, warp = tid >> 5;
    int wq = warp & 3, wc = warp >> 2;
    int lr = lane >> 2, lc = lane & 3;
    const float scale = 0.08838834764831844f;

    int r0 = wq * 16;
    int n0 = wc * 32;
    int h0c = wc * 64;

    for (int i = tid; i < 64 * 16; i += 256) {
        int r = i >> 4, c4 = (i & 15) << 2;
        size_t g = (((size_t)(b * T_ + qt * 64 + r)) * NH + n) * 64 + c4;
        *(uint4*)&QsH[r * QS_STRIDE + c4] = *(const uint4*)(Qh + g);
        *(uint4*)&QsL[r * QS_STRIDE + c4] = *(const uint4*)(Ql + g);
    }
    if (tid < 64) { mrow[tid] = -1e30f; lrow[tid] = 0.f; }

    float o[8][4];
#pragma unroll
    for (int nt = 0; nt < 8; nt++)
#pragma unroll
        for (int r = 0; r < 4; r++) o[nt][r] = 0.f;

    int row = tid >> 2, part = tid & 3;

    for (int kt = 0; kt <= qt; ++kt) {
        __syncthreads();

        for (int i = tid; i < 64 * 16; i += 256) {
            int r = i >> 4, c4 = (i & 15) << 2;
            size_t g = (((size_t)(b * T_ + kt * 64 + r)) * KH + kvh) * 64 + c4;
            *(uint4*)&KsH[r * QS_STRIDE + c4] = *(const uint4*)(Kh + g);
            *(uint4*)&KsL[r * QS_STRIDE + c4] = *(const uint4*)(Kl + g);
        }
        for (int i = tid; i < 32 * 32; i += 256) {
            int kp = i >> 5, h4 = (i & 31) << 2;
            size_t g = (((size_t)(b * (T_ / 2) + kt * 32 + kp)) * KH + kvh) * HD + h4;
            *(uint4*)&VsH[kp * VS_STRIDE + h4] = *(const uint4*)(Vh + g);
            *(uint4*)&VsL[kp * VS_STRIDE + h4] = *(const uint4*)(Vl + g);
        }
        __syncthreads();

        float s[4][4];
#pragma unroll
        for (int nt = 0; nt < 4; nt++)
#pragma unroll
            for (int r = 0; r < 4; r++) s[nt][r] = 0.f;

#pragma unroll
        for (int kc = 0; kc < 8; kc++) {
            int pa = 8 * kc + lc;
            int ra = (r0 + lr) * QS_STRIDE, rb = (r0 + 8 + lr) * QS_STRIDE;
            uint32_t aH[4], aL[4];
            aH[0] = QsH[ra + pa];     aH[1] = QsH[rb + pa];
            aH[2] = QsH[ra + pa + 4]; aH[3] = QsH[rb + pa + 4];
            aL[0] = QsL[ra + pa];     aL[1] = QsL[rb + pa];
            aL[2] = QsL[ra + pa + 4]; aL[3] = QsL[rb + pa + 4];
#pragma unroll
            for (int nt = 0; nt < 4; nt++) {
                int nn = (n0 + nt * 8 + lr) * QS_STRIDE;
                uint32_t bH[2] = {KsH[nn + pa], KsH[nn + pa + 4]};
                uint32_t bL[2] = {KsL[nn + pa], KsL[nn + pa + 4]};
                mma_bf16(s[nt], aH, bH);
                mma_bf16(s[nt], aH, bL);
                mma_bf16(s[nt], aL, bH);
            }
        }

        bool diag = (kt == qt);
        int rq0 = r0 + lr, rq1 = r0 + 8 + lr;
#pragma unroll
        for (int nt = 0; nt < 4; nt++) {
            int col = n0 + nt * 8 + (lc << 1);
            float v0 = s[nt][0] * scale, v1 = s[nt][1] * scale;
            float v2 = s[nt][2] * scale, v3 = s[nt][3] * scale;
            if (diag) {
                if (col     > rq0) v0 = -1e30f;
                if (col + 1 > rq0) v1 = -1e30f;
                if (col     > rq1) v2 = -1e30f;
                if (col + 1 > rq1) v3 = -1e30f;
            }
            Ss[rq0 * SS_STRIDE + col]     = v0;
            Ss[rq0 * SS_STRIDE + col + 1] = v1;
            Ss[rq1 * SS_STRIDE + col]     = v2;
            Ss[rq1 * SS_STRIDE + col + 1] = v3;
        }
        __syncthreads();

        float mx = -1e30f;
#pragma unroll
        for (int c = 0; c < 16; ++c)
            mx = fmaxf(mx, Ss[row * SS_STRIDE + part * 16 + c]);
        mx = fmaxf(mx, __shfl_xor_sync(0xffffffffu, mx, 1));
        mx = fmaxf(mx, __shfl_xor_sync(0xffffffffu, mx, 2));
        float m_old = mrow[row];
        float m_new = fmaxf(m_old, mx);
        float sum = 0.f;
#pragma unroll
        for (int c = 0; c < 16; ++c) {
            float p = __expf(Ss[row * SS_STRIDE + part * 16 + c] - m_new);
            Ss[row * SS_STRIDE + part * 16 + c] = p;
            sum += p;
        }
        sum += __shfl_xor_sync(0xffffffffu, sum, 1);
        sum += __shfl_xor_sync(0xffffffffu, sum, 2);
        if (part == 0) {
            float alpha = __expf(m_old - m_new);
            arow[row] = alpha;
            mrow[row] = m_new;
            lrow[row] = lrow[row] * alpha + sum;
        }
        __syncthreads();

        float al0 = arow[rq0], al1 = arow[rq1];
#pragma unroll
        for (int nt = 0; nt < 8; nt++) {
            o[nt][0] *= al0; o[nt][1] *= al0;
            o[nt][2] *= al1; o[nt][3] *= al1;
        }

#pragma unroll
        for (int kc = 0; kc < 4; kc++) {
            int ka = 16 * kc + (lc << 1);
            float2 p00 = *(float2*)&Ss[rq0 * SS_STRIDE + ka];
            float2 p01 = *(float2*)&Ss[rq0 * SS_STRIDE + ka + 8];
            float2 p10 = *(float2*)&Ss[rq1 * SS_STRIDE + ka];
            float2 p11 = *(float2*)&Ss[rq1 * SS_STRIDE + ka + 8];
            uint32_t aH[4], aL[4];
            split_pair(p00.x, p00.y, aH[0], aL[0]);
            split_pair(p10.x, p10.y, aH[1], aL[1]);
            split_pair(p01.x, p01.y, aH[2], aL[2]);
            split_pair(p11.x, p11.y, aH[3], aL[3]);
#pragma unroll
            for (int nt = 0; nt < 8; nt++) {
                int nn = h0c + nt * 8 + lr;
                int kpb = 8 * kc + lc;
                uint32_t bH[2] = {VsH[kpb * VS_STRIDE + nn], VsH[(kpb + 4) * VS_STRIDE + nn]};
                uint32_t bL[2] = {VsL[kpb * VS_STRIDE + nn], VsL[(kpb + 4) * VS_STRIDE + nn]};
                mma_bf16(o[nt], aH, bH);
                mma_bf16(o[nt], aH, bL);
                mma_bf16(o[nt], aL, bH);
            }
        }
    }

    // Fused epilogue: normalize + single fp16 pack into O-proj A-operand words.
    int rq0 = r0 + lr, rq1 = r0 + 8 + lr;
    float li0 = 1.f / lrow[rq0], li1 = 1.f / lrow[rq1];
    size_t ub0 = ((size_t)(b * T_ + qt * 64 + rq0)) * (NH * 64) + n * 64;
    size_t ub1 = ((size_t)(b * T_ + qt * 64 + rq1)) * (NH * 64) + n * 64;
#pragma unroll
    for (int nt = 0; nt < 8; nt++) {
        int colw = (h0c + nt * 8 + (lc << 1)) >> 1;
        __half2 h0 = __floats2half2_rn(o[nt][0] * li0, o[nt][1] * li0);
        __half2 h1 = __floats2half2_rn(o[nt][2] * li1, o[nt][3] * li1);
        At[ub0 + colw] = *reinterpret_cast<uint32_t*>(&h0);
        At[ub1 + colw] = *reinterpret_cast<uint32_t*>(&h1);
    }
}

// ============================================================================
// Launch  (order chosen so ncu -s 5 -c 1 captures the Q-projection GEMM)
// ============================================================================
extern "C" void kernel_launch(void* const* d_in, const int* in_sizes, int n_in,
                              void* d_out, int out_size)
{
    const float* Xq  = (const float*)d_in[0];
    const float* Xkv = (const float*)d_in[1];
    const int* qpos  = (const int*)d_in[2];
    const int* kvpos = (const int*)d_in[3];
    const float* Wq  = (const float*)d_in[4];
    const float* Wk  = (const float*)d_in[5];
    const float* Wv  = (const float*)d_in[6];
    const float* Wo  = (const float*)d_in[7];
    float* out = (float*)d_out;

    uint32_t *pXqh, *pXkvh, *pWqh, *pWql, *pWkvh, *pWkvl, *pWoh, *pWol;
    uint32_t *pQh, *pQl, *pKh, *pKl, *pVh, *pVl, *pAt;
    cudaGetSymbolAddress((void**)&pXqh, g_Xq_h);
    cudaGetSymbolAddress((void**)&pXkvh, g_Xkv_h);
    cudaGetSymbolAddress((void**)&pWqh, g_Wq_h);   cudaGetSymbolAddress((void**)&pWql, g_Wq_l);
    cudaGetSymbolAddress((void**)&pWkvh, g_Wkv_h); cudaGetSymbolAddress((void**)&pWkvl, g_Wkv_l);
    cudaGetSymbolAddress((void**)&pWoh, g_Wo_h);   cudaGetSymbolAddress((void**)&pWol, g_Wo_l);
    cudaGetSymbolAddress((void**)&pQh, g_Qh);      cudaGetSymbolAddress((void**)&pQl, g_Ql);
    cudaGetSymbolAddress((void**)&pKh, g_Kh);      cudaGetSymbolAddress((void**)&pKl, g_Kl);
    cudaGetSymbolAddress((void**)&pVh, g_Vh);      cudaGetSymbolAddress((void**)&pVl, g_Vl);
    cudaGetSymbolAddress((void**)&pAt, g_At_h);

    cudaFuncSetAttribute(flash_kernel,
                         cudaFuncAttributeMaxDynamicSharedMemorySize, FLASH_SMEM_BYTES);
    cudaFuncSetAttribute(f16p_gemm_kernel,
                         cudaFuncAttributeMaxDynamicSharedMemorySize, GEMM_SMEM_BYTES);

    int M = B_ * T_;  // 4096

    // 1-4: weight fp16 hi/lo splits
    int wWq = (D_ / 2) * (NH * HD);
    f16_colpair_kernel<<<(wWq + 255) / 256, 256>>>(Wq, pWqh, pWql, NH * HD, NH * HD, 0, wWq);
    int wWk = (D_ / 2) * (KH * HD);
    f16_colpair_kernel<<<(wWk + 255) / 256, 256>>>(Wk, pWkvh, pWkvl, KH * HD, 2 * KH * HD, 0, wWk);
    f16_colpair_kernel<<<(wWk + 255) / 256, 256>>>(Wv, pWkvh, pWkvl, KH * HD, 2 * KH * HD, KH * HD, wWk);
    int wWo = ((NH * HD) / 2) * D_;
    f16_colpair_kernel<<<(wWo + 255) / 256, 256>>>(Wo, pWoh, pWol, D_, D_, 0, wWo);

    // 5: Xq fp16 pack
    int wX = M * D_ / 2;
    f16_rowpair_kernel<<<(wX + 255) / 256, 256>>>(Xq, pXqh, wX);

    // 6: Q projection + fused RoPE/split  (ncu -s 5 -c 1 captures this launch)
    f16p_gemm_kernel<<<dim3((NH * HD) / 128, M / 256), 256, GEMM_SMEM_BYTES>>>(
        pXqh, pWqh, pWql, nullptr, pQh, pQl, nullptr, nullptr, qpos,
        M, NH * HD, D_ / 2, 1);

    // 7: Xkv fp16 pack
    f16_rowpair_kernel<<<(wX + 255) / 256, 256>>>(Xkv, pXkvh, wX);

    // 8: KV projection + fused RoPE-K / V-pair split
    f16p_gemm_kernel<<<dim3((2 * KH * HD) / 128, M / 256), 256, GEMM_SMEM_BYTES>>>(
        pXkvh, pWkvh, pWkvl, nullptr, pKh, pKl, pVh, pVl, kvpos,
        M, 2 * KH * HD, D_ / 2, 2);

    // 9: flash attention (bf16 3-product core, fp16 attn epilogue)
    flash_kernel<<<dim3(T_ / 64, NH, B_), 256, FLASH_SMEM_BYTES>>>(
        pQh, pQl, pKh, pKl, pVh, pVl, pAt);

    // 10: O projection (fp32 out)
    f16p_gemm_kernel<<<dim3(D_ / 128, M / 256), 256, GEMM_SMEM_BYTES>>>(
        pAt, pWoh, pWol, out, nullptr, nullptr, nullptr, nullptr, nullptr,
        M, D_, (NH * HD) / 2, 0);
}